// round 13
// baseline (speedup 1.0000x reference)
#include <cuda_runtime.h>
#include <math.h>

#define BOUND 10.0f
#define EPSF  1e-6f
#define MIN_SCALE 1e-4f

#define MAXD 1024
#define K64  64
#define CELLS 256
#define CELLS_PER_UNIT (256.0f / 20.0f)   // 12.8

// Precomputed packed spline tables (scratch; allocation-free per harness rules)
__device__ float4 g_P0[MAXD * K64];       // {x0, 1/w, y0, h}
__device__ float4 g_P1[MAXD * K64];       // {d0, d0+d1-2*s, x_{k+1}, 0}
__device__ unsigned int g_tab[MAXD * (CELLS / 4)];  // 4 packed u8 lower-bound idx per cell
__device__ float g_scale[MAXD];

__device__ __forceinline__ float softplusf(float x) {
    return (x > 20.0f) ? x : log1pf(__expf(x));
}

// Warp-per-dim preproc: 8 dims/block (256 thr), shfl-only softmax + scan.
// Lane L owns entries L and L+32 of each K=64 vector.
#define PRE_DIMS 8
__global__ void __launch_bounds__(256)
spline_preproc_kernel(const float* __restrict__ raw_w,
                      const float* __restrict__ raw_h,
                      const float* __restrict__ raw_s,
                      const float* __restrict__ log_scale) {
    const int warp = threadIdx.x >> 5, lane = threadIdx.x & 31;
    const int d = blockIdx.x * PRE_DIMS + warp;

    __shared__ float xs_s[PRE_DIMS][K64 + 1];
    __shared__ float ys_s[PRE_DIMS][K64 + 1];
    __shared__ float sl_s[PRE_DIMS][K64 + 1];
    float* xs = xs_s[warp];
    float* ys = ys_s[warp];
    float* sl = sl_s[warp];

    // ---- widths: softmax * 2B ----
    float w0 = raw_w[d * K64 + lane], w1 = raw_w[d * K64 + 32 + lane];
    float m = fmaxf(w0, w1);
    #pragma unroll
    for (int off = 16; off > 0; off >>= 1) m = fmaxf(m, __shfl_xor_sync(0xffffffffu, m, off));
    float e0 = __expf(w0 - m), e1 = __expf(w1 - m);
    float es = e0 + e1;
    #pragma unroll
    for (int off = 16; off > 0; off >>= 1) es += __shfl_xor_sync(0xffffffffu, es, off);
    float norm = (2.0f * BOUND) / es;
    float ww0 = e0 * norm, ww1 = e1 * norm;

    // ---- heights: softmax * 2B ----
    float h0 = raw_h[d * K64 + lane], h1 = raw_h[d * K64 + 32 + lane];
    float mh = fmaxf(h0, h1);
    #pragma unroll
    for (int off = 16; off > 0; off >>= 1) mh = fmaxf(mh, __shfl_xor_sync(0xffffffffu, mh, off));
    float f0 = __expf(h0 - mh), f1 = __expf(h1 - mh);
    float fs = f0 + f1;
    #pragma unroll
    for (int off = 16; off > 0; off >>= 1) fs += __shfl_xor_sync(0xffffffffu, fs, off);
    float normh = (2.0f * BOUND) / fs;
    float hh0 = f0 * normh, hh1 = f1 * normh;

    // ---- inclusive scans (two half-vectors in parallel) ----
    float sa = ww0, sb = ww1, sc = hh0, sd = hh1;
    #pragma unroll
    for (int off = 1; off < 32; off <<= 1) {
        float ta = __shfl_up_sync(0xffffffffu, sa, off);
        float tb = __shfl_up_sync(0xffffffffu, sb, off);
        float tc = __shfl_up_sync(0xffffffffu, sc, off);
        float td = __shfl_up_sync(0xffffffffu, sd, off);
        if (lane >= off) { sa += ta; sb += tb; sc += tc; sd += td; }
    }
    const float Aw = __shfl_sync(0xffffffffu, sa, 31);
    const float Ah = __shfl_sync(0xffffffffu, sc, 31);

    xs[lane + 1]  = sa - BOUND;
    xs[lane + 33] = (Aw + sb) - BOUND;
    ys[lane + 1]  = sc - BOUND;
    ys[lane + 33] = (Ah + sd) - BOUND;
    if (lane == 0) { xs[0] = -BOUND; ys[0] = -BOUND; }

    // ---- slopes ----
    sl[lane]      = softplusf(raw_s[d * (K64 + 1) + lane]);
    sl[lane + 32] = softplusf(raw_s[d * (K64 + 1) + 32 + lane]);
    if (lane == 0) {
        sl[K64] = softplusf(raw_s[d * (K64 + 1) + K64]);
        g_scale[d] = softplusf(log_scale[d]) + MIN_SCALE;
    }
    __syncwarp();

    // ---- pack per-interval params (t = lane, lane+32) ----
    {
        int t = lane;
        float invw = 1.0f / ww0;
        float s = hh0 * invw;
        g_P0[d * K64 + t] = make_float4(xs[t], invw, ys[t], hh0);
        g_P1[d * K64 + t] = make_float4(sl[t], sl[t] + sl[t + 1] - 2.0f * s, xs[t + 1], 0.0f);
        t = lane + 32;
        invw = 1.0f / ww1;
        s = hh1 * invw;
        g_P0[d * K64 + t] = make_float4(xs[t], invw, ys[t], hh1);
        g_P1[d * K64 + t] = make_float4(sl[t], sl[t] + sl[t + 1] - 2.0f * s, xs[t + 1], 0.0f);
    }

    // ---- cell table: 8 cells per lane ----
    {
        unsigned int packed0 = 0, packed1 = 0;
        #pragma unroll
        for (int j = 0; j < 8; j++) {
            const int c = lane * 8 + j;
            const float left = -BOUND + (float)c * (20.0f / (float)CELLS);
            int idx = 0;
            #pragma unroll
            for (int st = 32; st > 0; st >>= 1) {
                int cand = idx + st;
                if (cand <= K64 - 1 && xs[cand] <= left) idx = cand;
            }
            if (j < 4) packed0 |= ((unsigned int)idx) << (8 * j);
            else       packed1 |= ((unsigned int)idx) << (8 * (j - 4));
        }
        g_tab[d * (CELLS / 4) + lane * 2 + 0] = packed0;
        g_tab[d * (CELLS / 4) + lane * 2 + 1] = packed1;
    }
}

// Main kernel: DTILE=16 dims/block; each thread owns 4 consecutive dims
// (float4 chunk of u/out); rgrp = tid>>2 -> 64 rows/block-iter; software-
// pipelined u/tau prefetch. Additive smem swizzle keeps LDS phases
// conflict-free. Probe is folded into the param gather: P1.z holds x_{k+1},
// so refinement re-loads P0/P1 only when the table's lower bound is short
// (p ~ 0.25) instead of paying a dedicated probe LDS every element.
#define DTILE 16
#define TPB   256
#define STRD  65           // padded per-dim stride (entries)
#define TABSTRD 260        // padded tab stride (bytes)
#define GRIDY 11           // 64*11=704 blocks (best-measured config)

__global__ void __launch_bounds__(TPB)
rqs_main_kernel(const float* __restrict__ u,
                const float* __restrict__ tau,
                const float* __restrict__ bias,
                float* __restrict__ out,
                int B, int D) {
    __shared__ float4 sP0[DTILE * STRD];            // 16640 B
    __shared__ float4 sP1[DTILE * STRD];            // 16640 B
    __shared__ unsigned char sTab[DTILE * TABSTRD]; //  4160 B
    __shared__ float sScale[DTILE], sBias[DTILE];

    const int d0 = blockIdx.x * DTILE;

    // Stage tables with the additive swizzle: slot (k + dim>>2) & 63.
    for (int i = threadIdx.x; i < DTILE * K64; i += TPB) {
        const int dim = i >> 6, k = i & 63;
        const int kp = (k + (dim >> 2)) & 63;
        sP0[dim * STRD + kp] = g_P0[d0 * K64 + i];
        sP1[dim * STRD + kp] = g_P1[d0 * K64 + i];
    }
    for (int i = threadIdx.x; i < DTILE * (CELLS / 4); i += TPB) {
        const int dim = i >> 6, j = i & 63;
        *(unsigned int*)(sTab + dim * TABSTRD + 4 * j) = g_tab[d0 * (CELLS / 4) + i];
    }
    if (threadIdx.x < DTILE) {
        sScale[threadIdx.x] = g_scale[d0 + threadIdx.x];
        sBias[threadIdx.x]  = bias[d0 + threadIdx.x];
    }
    __syncthreads();

    const int laned = threadIdx.x & 3;               // 0..3: which float4 chunk
    const int rgrp  = threadIdx.x >> 2;              // 0..63: row group
    const int dbase = 4 * laned;                     // local dim base (0,4,8,12)

    const float sc0 = sScale[dbase + 0], sc1 = sScale[dbase + 1],
                sc2 = sScale[dbase + 2], sc3 = sScale[dbase + 3];
    const float bi0 = sBias[dbase + 0], bi1 = sBias[dbase + 1],
                bi2 = sBias[dbase + 2], bi3 = sBias[dbase + 3];

    const int rowsPerIter = TPB / 4;                 // 64
    const int rstride = gridDim.y * rowsPerIter;

    int r = blockIdx.y * rowsPerIter + rgrp;

    // ---- prefetch iteration 0 ----
    float4 u4 = make_float4(0.f, 0.f, 0.f, 0.f);
    float tv = 0.f;
    if (r < B) {
        u4 = *(const float4*)(u + (size_t)r * D + d0 + dbase);
        tv = __ldg(tau + r);
    }

    while (r < B) {
        const int rn = r + rstride;
        // ---- prefetch next iteration's global data (hides LDG latency) ----
        float4 u4n;
        float tvn;
        if (rn < B) {
            u4n = *(const float4*)(u + (size_t)rn * D + d0 + dbase);
            tvn = __ldg(tau + rn);
        }

        float zz[4];
        {
            const float ua[4] = {u4.x, u4.y, u4.z, u4.w};
            #pragma unroll
            for (int jj = 0; jj < 4; jj++) {
                const float us = fminf(fmaxf(ua[jj], EPSF), 1.0f - EPSF);
                zz[jj] = __logf(__fdividef(us, 1.0f - us));
            }
        }

        // batched table lookups (lower bound)
        int idx[4];
        #pragma unroll
        for (int jj = 0; jj < 4; jj++) {
            int c = (int)fmaf(zz[jj], CELLS_PER_UNIT, (float)(CELLS / 2));
            c = max(0, min(CELLS - 1, c));
            idx[jj] = sTab[(dbase + jj) * TABSTRD + c];
        }

        // fused gather + refinement + eval per chain
        float res[4];
        #pragma unroll
        for (int jj = 0; jj < 4; jj++) {
            const float z = zz[jj];
            const float4* P0 = sP0 + (dbase + jj) * STRD;
            const float4* P1 = sP1 + (dbase + jj) * STRD;
            int i0 = idx[jj];
            float4 p = P0[(i0 + laned) & 63];
            float4 q = P1[(i0 + laned) & 63];
            while (i0 < K64 - 1 && q.z <= z) {       // q.z = x_{k+1}; rare (~25%)
                ++i0;
                p = P0[(i0 + laned) & 63];
                q = P1[(i0 + laned) & 63];
            }
            if (z > -BOUND && z < BOUND) {
                const float theta = (z - p.x) * p.y;
                const float t1m = theta * (1.0f - theta);
                const float s = p.w * p.y;           // h/w
                const float den = fmaf(q.y, t1m, s);
                const float num = fmaf(s * theta, theta, q.x * t1m);
                res[jj] = fmaf(p.w, __fdividef(num, den), p.z);
            } else {
                res[jj] = z;
            }
        }

        float4 o4;
        o4.x = tv * fmaf(res[0], sc0, bi0);
        o4.y = tv * fmaf(res[1], sc1, bi1);
        o4.z = tv * fmaf(res[2], sc2, bi2);
        o4.w = tv * fmaf(res[3], sc3, bi3);
        *(float4*)(out + (size_t)r * D + d0 + dbase) = o4;

        u4 = u4n;
        tv = tvn;
        r = rn;
    }
}

extern "C" void kernel_launch(void* const* d_in, const int* in_sizes, int n_in,
                              void* d_out, int out_size) {
    const float* u         = (const float*)d_in[0];
    const float* tau       = (const float*)d_in[1];
    const float* log_scale = (const float*)d_in[2];
    const float* bias      = (const float*)d_in[3];
    const float* raw_w     = (const float*)d_in[4];
    const float* raw_h     = (const float*)d_in[5];
    const float* raw_s     = (const float*)d_in[6];
    float* out = (float*)d_out;

    const int D = in_sizes[2];
    const int B = in_sizes[0] / D;

    spline_preproc_kernel<<<D / PRE_DIMS, 256>>>(raw_w, raw_h, raw_s, log_scale);

    dim3 grid(D / DTILE, GRIDY);
    rqs_main_kernel<<<grid, TPB>>>(u, tau, bias, out, B, D);
}

// round 15
// speedup vs baseline: 1.0856x; 1.0856x over previous
#include <cuda_runtime.h>
#include <math.h>

#define BOUND 10.0f
#define EPSF  1e-6f
#define MIN_SCALE 1e-4f

#define MAXD 1024
#define K64  64
#define CELLS 512
#define CELLS_PER_UNIT (512.0f / 20.0f)   // 25.6
#define CELL_W (20.0f / 512.0f)

// Precomputed packed spline tables (scratch; allocation-free per harness rules)
__device__ float4 g_P0[MAXD * K64];       // {x0, 1/w, y0, h}
__device__ float2 g_P1[MAXD * K64];       // {d0, d0 + d1 - 2*s}
__device__ unsigned int g_tab[MAXD * (CELLS / 4)];  // packed u8 lower-bound idx per cell
__device__ float g_scale[MAXD];

__device__ __forceinline__ float softplusf(float x) {
    return (x > 20.0f) ? x : log1pf(__expf(x));
}

// Warp-per-dim preproc: 8 dims/block (256 thr), shfl-only softmax + scan.
// Lane L owns entries L and L+32 of each K=64 vector.
#define PRE_DIMS 8
__global__ void __launch_bounds__(256)
spline_preproc_kernel(const float* __restrict__ raw_w,
                      const float* __restrict__ raw_h,
                      const float* __restrict__ raw_s,
                      const float* __restrict__ log_scale) {
    const int warp = threadIdx.x >> 5, lane = threadIdx.x & 31;
    const int d = blockIdx.x * PRE_DIMS + warp;

    __shared__ float xs_s[PRE_DIMS][K64 + 1];
    __shared__ float ys_s[PRE_DIMS][K64 + 1];
    __shared__ float sl_s[PRE_DIMS][K64 + 1];
    float* xs = xs_s[warp];
    float* ys = ys_s[warp];
    float* sl = sl_s[warp];

    // ---- widths: softmax * 2B ----
    float w0 = raw_w[d * K64 + lane], w1 = raw_w[d * K64 + 32 + lane];
    float m = fmaxf(w0, w1);
    #pragma unroll
    for (int off = 16; off > 0; off >>= 1) m = fmaxf(m, __shfl_xor_sync(0xffffffffu, m, off));
    float e0 = __expf(w0 - m), e1 = __expf(w1 - m);
    float es = e0 + e1;
    #pragma unroll
    for (int off = 16; off > 0; off >>= 1) es += __shfl_xor_sync(0xffffffffu, es, off);
    float norm = (2.0f * BOUND) / es;
    float ww0 = e0 * norm, ww1 = e1 * norm;

    // ---- heights: softmax * 2B ----
    float h0 = raw_h[d * K64 + lane], h1 = raw_h[d * K64 + 32 + lane];
    float mh = fmaxf(h0, h1);
    #pragma unroll
    for (int off = 16; off > 0; off >>= 1) mh = fmaxf(mh, __shfl_xor_sync(0xffffffffu, mh, off));
    float f0 = __expf(h0 - mh), f1 = __expf(h1 - mh);
    float fs = f0 + f1;
    #pragma unroll
    for (int off = 16; off > 0; off >>= 1) fs += __shfl_xor_sync(0xffffffffu, fs, off);
    float normh = (2.0f * BOUND) / fs;
    float hh0 = f0 * normh, hh1 = f1 * normh;

    // ---- inclusive scans (two half-vectors in parallel) ----
    float sa = ww0, sb = ww1, sc = hh0, sd = hh1;
    #pragma unroll
    for (int off = 1; off < 32; off <<= 1) {
        float ta = __shfl_up_sync(0xffffffffu, sa, off);
        float tb = __shfl_up_sync(0xffffffffu, sb, off);
        float tc = __shfl_up_sync(0xffffffffu, sc, off);
        float td = __shfl_up_sync(0xffffffffu, sd, off);
        if (lane >= off) { sa += ta; sb += tb; sc += tc; sd += td; }
    }
    const float Aw = __shfl_sync(0xffffffffu, sa, 31);
    const float Ah = __shfl_sync(0xffffffffu, sc, 31);

    xs[lane + 1]  = sa - BOUND;
    xs[lane + 33] = (Aw + sb) - BOUND;
    ys[lane + 1]  = sc - BOUND;
    ys[lane + 33] = (Ah + sd) - BOUND;
    if (lane == 0) { xs[0] = -BOUND; ys[0] = -BOUND; }

    // ---- slopes ----
    sl[lane]      = softplusf(raw_s[d * (K64 + 1) + lane]);
    sl[lane + 32] = softplusf(raw_s[d * (K64 + 1) + 32 + lane]);
    if (lane == 0) {
        sl[K64] = softplusf(raw_s[d * (K64 + 1) + K64]);
        g_scale[d] = softplusf(log_scale[d]) + MIN_SCALE;
    }
    __syncwarp();

    // ---- pack per-interval params (t = lane, lane+32) ----
    {
        int t = lane;
        float invw = 1.0f / ww0;
        float s = hh0 * invw;
        g_P0[d * K64 + t] = make_float4(xs[t], invw, ys[t], hh0);
        g_P1[d * K64 + t] = make_float2(sl[t], sl[t] + sl[t + 1] - 2.0f * s);
        t = lane + 32;
        invw = 1.0f / ww1;
        s = hh1 * invw;
        g_P0[d * K64 + t] = make_float4(xs[t], invw, ys[t], hh1);
        g_P1[d * K64 + t] = make_float2(sl[t], sl[t] + sl[t + 1] - 2.0f * s);
    }

    // ---- cell table: 16 cells per lane (CELLS=512) ----
    // Lower-bound index for (cell left edge - 1e-4): the margin makes the
    // table a valid lower bound even under fp rounding of the cell index.
    {
        #pragma unroll
        for (int q = 0; q < 4; q++) {
            unsigned int packed = 0;
            #pragma unroll
            for (int j = 0; j < 4; j++) {
                const int c = lane * 16 + q * 4 + j;
                const float left = fmaf((float)c, CELL_W, -BOUND - 1e-4f);
                int idx = 0;
                #pragma unroll
                for (int st = 32; st > 0; st >>= 1) {
                    int cand = idx + st;
                    if (cand <= K64 - 1 && xs[cand] <= left) idx = cand;
                }
                packed |= ((unsigned int)idx) << (8 * j);
            }
            g_tab[d * (CELLS / 4) + lane * 4 + q] = packed;
        }
    }
}

// Main kernel (R12 structure, CELLS=512): DTILE=16 dims/block; each thread
// owns 4 consecutive dims (float4 chunk of u/out); rgrp = tid>>2 -> 64
// rows/block-iter; software-pipelined u/tau prefetch. Additive smem swizzle
// keeps LDS phases conflict-free. 512-cell table cuts expected scalar
// probes ~4x vs 256 cells.
#define DTILE 16
#define TPB   256
#define STRD  65           // padded per-dim stride (entries)
#define TABSTRD 516        // padded tab stride (bytes): 516 = 4*129, 129 odd mod 32
#define GRIDY 11           // 64*11=704 blocks (best-measured config)

__global__ void __launch_bounds__(TPB)
rqs_main_kernel(const float* __restrict__ u,
                const float* __restrict__ tau,
                const float* __restrict__ bias,
                float* __restrict__ out,
                int B, int D) {
    __shared__ float4 sP0[DTILE * STRD];            // 16640 B
    __shared__ float2 sP1[DTILE * STRD];            //  8320 B
    __shared__ float  sXK[DTILE * STRD];            //  4160 B
    __shared__ unsigned char sTab[DTILE * TABSTRD]; //  8256 B
    __shared__ float sScale[DTILE], sBias[DTILE];

    const int d0 = blockIdx.x * DTILE;

    // Stage tables with the additive swizzle: slot (k + dim>>2) & 63.
    for (int i = threadIdx.x; i < DTILE * K64; i += TPB) {
        const int dim = i >> 6, k = i & 63;
        const int kp = (k + (dim >> 2)) & 63;
        const float4 p = g_P0[d0 * K64 + i];
        sP0[dim * STRD + kp] = p;
        sXK[dim * STRD + kp] = p.x;
        sP1[dim * STRD + kp] = g_P1[d0 * K64 + i];
    }
    for (int i = threadIdx.x; i < DTILE * (CELLS / 4); i += TPB) {
        const int dim = i >> 7, j = i & 127;        // CELLS/4 = 128 words per dim
        *(unsigned int*)(sTab + dim * TABSTRD + 4 * j) = g_tab[d0 * (CELLS / 4) + i];
    }
    if (threadIdx.x < DTILE) {
        sScale[threadIdx.x] = g_scale[d0 + threadIdx.x];
        sBias[threadIdx.x]  = bias[d0 + threadIdx.x];
    }
    __syncthreads();

    const int laned = threadIdx.x & 3;               // 0..3: which float4 chunk
    const int rgrp  = threadIdx.x >> 2;              // 0..63: row group
    const int dbase = 4 * laned;                     // local dim base (0,4,8,12)

    const float sc0 = sScale[dbase + 0], sc1 = sScale[dbase + 1],
                sc2 = sScale[dbase + 2], sc3 = sScale[dbase + 3];
    const float bi0 = sBias[dbase + 0], bi1 = sBias[dbase + 1],
                bi2 = sBias[dbase + 2], bi3 = sBias[dbase + 3];

    const int rowsPerIter = TPB / 4;                 // 64
    const int rstride = gridDim.y * rowsPerIter;

    int r = blockIdx.y * rowsPerIter + rgrp;

    // ---- prefetch iteration 0 ----
    float4 u4 = make_float4(0.f, 0.f, 0.f, 0.f);
    float tv = 0.f;
    if (r < B) {
        u4 = *(const float4*)(u + (size_t)r * D + d0 + dbase);
        tv = __ldg(tau + r);
    }

    while (r < B) {
        const int rn = r + rstride;
        // ---- prefetch next iteration's global data (hides LDG latency) ----
        float4 u4n;
        float tvn;
        if (rn < B) {
            u4n = *(const float4*)(u + (size_t)rn * D + d0 + dbase);
            tvn = __ldg(tau + rn);
        }

        float zz[4];
        {
            const float ua[4] = {u4.x, u4.y, u4.z, u4.w};
            #pragma unroll
            for (int jj = 0; jj < 4; jj++) {
                const float us = fminf(fmaxf(ua[jj], EPSF), 1.0f - EPSF);
                zz[jj] = __logf(__fdividef(us, 1.0f - us));
            }
        }

        // batched table lookups (lower bound)
        int idx[4];
        #pragma unroll
        for (int jj = 0; jj < 4; jj++) {
            int c = (int)fmaf(zz[jj], CELLS_PER_UNIT, (float)(CELLS / 2));
            c = max(0, min(CELLS - 1, c));
            idx[jj] = sTab[(dbase + jj) * TABSTRD + c];
        }

        // refinement: rare with 512 cells (~0.15 probes/chain)
        #pragma unroll
        for (int jj = 0; jj < 4; jj++) {
            const float* xs = sXK + (dbase + jj) * STRD;
            int nxt = idx[jj] + 1;
            while (nxt < K64 && xs[(nxt + laned) & 63] <= zz[jj]) { idx[jj] = nxt; ++nxt; }
        }

        float res[4];
        #pragma unroll
        for (int jj = 0; jj < 4; jj++) {
            const float z = zz[jj];
            if (z > -BOUND && z < BOUND) {
                const int kp = (idx[jj] + laned) & 63;
                const float4 p = sP0[(dbase + jj) * STRD + kp];  // {x0,1/w,y0,h}
                const float2 q = sP1[(dbase + jj) * STRD + kp];  // {d0,d0+d1-2s}
                const float theta = (z - p.x) * p.y;
                const float t1m = theta * (1.0f - theta);
                const float s = p.w * p.y;                       // h/w
                const float den = fmaf(q.y, t1m, s);
                const float num = fmaf(s * theta, theta, q.x * t1m);
                res[jj] = fmaf(p.w, __fdividef(num, den), p.z);
            } else {
                res[jj] = z;
            }
        }

        float4 o4;
        o4.x = tv * fmaf(res[0], sc0, bi0);
        o4.y = tv * fmaf(res[1], sc1, bi1);
        o4.z = tv * fmaf(res[2], sc2, bi2);
        o4.w = tv * fmaf(res[3], sc3, bi3);
        *(float4*)(out + (size_t)r * D + d0 + dbase) = o4;

        u4 = u4n;
        tv = tvn;
        r = rn;
    }
}

extern "C" void kernel_launch(void* const* d_in, const int* in_sizes, int n_in,
                              void* d_out, int out_size) {
    const float* u         = (const float*)d_in[0];
    const float* tau       = (const float*)d_in[1];
    const float* log_scale = (const float*)d_in[2];
    const float* bias      = (const float*)d_in[3];
    const float* raw_w     = (const float*)d_in[4];
    const float* raw_h     = (const float*)d_in[5];
    const float* raw_s     = (const float*)d_in[6];
    float* out = (float*)d_out;

    const int D = in_sizes[2];
    const int B = in_sizes[0] / D;

    spline_preproc_kernel<<<D / PRE_DIMS, 256>>>(raw_w, raw_h, raw_s, log_scale);

    dim3 grid(D / DTILE, GRIDY);
    rqs_main_kernel<<<grid, TPB>>>(u, tau, bias, out, B, D);
}